// round 1
// baseline (speedup 1.0000x reference)
#include <cuda_runtime.h>
#include <cuda_bf16.h>
#include <math.h>

// ---------------- problem constants ----------------
#define Bsz  8
#define Lseq 2049
#define Dmod 256
#define DI   512
#define DS   16
#define DRK  16
#define LB   1025    // per-branch input length (mid = L//2+1 = 1025)
#define LC   1028    // conv output length: 1025 + 2*3 - 4 + 1
#define Stok 64
#define NXP  48      // dt_rank + 2*d_state

// ---------------- scratch (device globals; no cudaMalloc allowed) ----------------
__device__ float g_xi[Bsz*Lseq*DI];
__device__ float g_uf[Bsz*LC*DI];
__device__ float g_ub[Bsz*LC*DI];
__device__ float g_dbcf[Bsz*LC*NXP];
__device__ float g_dbcb[Bsz*LC*NXP];
__device__ float g_deltaf[Bsz*LC*DI];
__device__ float g_deltab[Bsz*LC*DI];
__device__ float g_yf[Bsz*LC*DI];
__device__ float g_yb[Bsz*LC*DI];
__device__ float g_ycat[Bsz*LC*2*DI];
__device__ float g_y[Bsz*LC*DI];
__device__ float g_mf[Bsz*LC];
__device__ float g_mb[Bsz*LC];
__device__ float g_mc[Bsz*LC];
__device__ float g_dist[Bsz*LC];
__device__ float g_xp[Bsz*Stok*Dmod];
__device__ float g_zp[Bsz*Stok*DI];
__device__ float g_scores[Bsz*LC*Stok];
__device__ float g_atok[Bsz*Stok*LC];
__device__ float g_vv[Bsz*LC*DI];
__device__ float g_T[Bsz*Stok*DI];

// ---------------- generic fp32 tiled GEMM ----------------
// C[M,N] = A[M,K(lda)] * op(B) (+bias per col) (act) (* emul elementwise)
// TB=0: B is (K,N) row-major ldb; TB=1: B is (N,K) row-major ldb.
// act: 0 none, 1 silu, 2 softplus.  Batched via gridDim.z with strides.
#define BM 128
#define BN 64
#define BK 16

template<int TB>
__global__ __launch_bounds__(256)
void sgemm_k(const float* __restrict__ A, const float* __restrict__ Bm,
             const float* __restrict__ bias, const float* __restrict__ emul,
             float* __restrict__ C,
             int M, int N, int K, int lda, int ldb, int ldc,
             long long sA, long long sB, long long sC, long long sE,
             int act)
{
    __shared__ float As[BK][BM+1];
    __shared__ float Bs[BK][BN+1];
    int bz = blockIdx.z;
    A  += (long long)bz * sA;
    Bm += (long long)bz * sB;
    C  += (long long)bz * sC;
    const float* em = emul ? emul + (long long)bz * sE : nullptr;

    int row0 = blockIdx.y * BM;
    int col0 = blockIdx.x * BN;
    int tx = threadIdx.x, ty = threadIdx.y;
    int tid = ty * 16 + tx;

    float acc[8][4];
    #pragma unroll
    for (int i = 0; i < 8; i++)
        #pragma unroll
        for (int j = 0; j < 4; j++) acc[i][j] = 0.f;

    for (int k0 = 0; k0 < K; k0 += BK) {
        // A tile: 128x16 -> 8 per thread
        #pragma unroll
        for (int i = 0; i < 8; i++) {
            int idx = tid + i * 256;
            int m = idx >> 4, kk = idx & 15;
            int gm = row0 + m, gk = k0 + kk;
            float v = 0.f;
            if (gm < M && gk < K) v = A[(long long)gm * lda + gk];
            As[kk][m] = v;
        }
        // B tile: 16x64 -> 4 per thread
        #pragma unroll
        for (int i = 0; i < 4; i++) {
            int idx = tid + i * 256;
            float v = 0.f;
            if (TB == 0) {
                int kk = idx >> 6, n = idx & 63;
                int gk = k0 + kk, gn = col0 + n;
                if (gk < K && gn < N) v = Bm[(long long)gk * ldb + gn];
                Bs[kk][n] = v;
            } else {
                int n = idx >> 4, kk = idx & 15;
                int gn = col0 + n, gk = k0 + kk;
                if (gn < N && gk < K) v = Bm[(long long)gn * ldb + gk];
                Bs[kk][n] = v;
            }
        }
        __syncthreads();
        #pragma unroll
        for (int kk = 0; kk < BK; kk++) {
            float a[8], b[4];
            #pragma unroll
            for (int i = 0; i < 8; i++) a[i] = As[kk][ty * 8 + i];
            #pragma unroll
            for (int j = 0; j < 4; j++) b[j] = Bs[kk][tx * 4 + j];
            #pragma unroll
            for (int i = 0; i < 8; i++)
                #pragma unroll
                for (int j = 0; j < 4; j++)
                    acc[i][j] = fmaf(a[i], b[j], acc[i][j]);
        }
        __syncthreads();
    }

    #pragma unroll
    for (int i = 0; i < 8; i++) {
        int gm = row0 + ty * 8 + i;
        if (gm >= M) continue;
        #pragma unroll
        for (int j = 0; j < 4; j++) {
            int gn = col0 + tx * 4 + j;
            if (gn >= N) continue;
            float v = acc[i][j];
            if (bias) v += bias[gn];
            if (act == 1)      v = v / (1.f + expf(-v));
            else if (act == 2) v = (v > 20.f) ? v : log1pf(expf(v));
            if (em) v *= em[(long long)gm * ldc + gn];
            C[(long long)gm * ldc + gn] = v;
        }
    }
}

// ---------------- pooling of x (P @ x), then zp via tiny GEMM ----------------
__global__ void pool_kernel(const float* __restrict__ x)
{
    int s = blockIdx.x, b = blockIdx.y, d = threadIdx.x; // 256 threads
    int s0 = (s * Lseq) / Stok;
    int e  = ((s + 1) * Lseq + Stok - 1) / Stok;
    float acc = 0.f;
    for (int l = s0; l < e; l++) acc += x[((long long)b * Lseq + l) * Dmod + d];
    g_xp[((long long)b * Stok + s) * Dmod + d] = acc / (float)(e - s0);
}

// ---------------- depthwise conv (k=4, pad 3) + SiLU ----------------
__global__ void conv_silu_kernel(const float* __restrict__ xi, const float* __restrict__ w,
                                 const float* __restrict__ bias, float* __restrict__ out,
                                 int backward)
{
    int t = blockIdx.x;      // 0..LC-1
    int b = blockIdx.y;
    int c = threadIdx.x;     // 0..511
    float acc = bias[c];
    #pragma unroll
    for (int k = 0; k < 4; k++) {
        int i = t + k - 3;
        if (i >= 0 && i < LB) {
            int l = backward ? (Lseq - 1 - i) : i;
            acc = fmaf(w[c * 4 + k], xi[((long long)b * Lseq + l) * DI + c], acc);
        }
    }
    out[((long long)b * LC + t) * DI + c] = acc / (1.f + expf(-acc));
}

// ---------------- selective scan: 16 lanes per (b,d), one state per lane ----------------
__global__ __launch_bounds__(256)
void scan_kernel(const float* __restrict__ u, const float* __restrict__ delta,
                 const float* __restrict__ dbc, const float* __restrict__ A_log,
                 const float* __restrict__ Dp, float* __restrict__ y)
{
    int gid = blockIdx.x * 16 + (threadIdx.x >> 4);
    int s = threadIdx.x & 15;
    int b = gid >> 9;
    int d = gid & 511;
    float Av = -expf(A_log[d * 16 + s]);
    float Dd = Dp[d];
    float h = 0.f;
    const float* db = dbc + (long long)b * LC * NXP;
    const float* dl = delta + ((long long)b * LC) * DI + d;
    const float* uu = u     + ((long long)b * LC) * DI + d;
    float*       yy = y     + ((long long)b * LC) * DI + d;
    for (int t = 0; t < LC; t++) {
        float de = __ldg(dl + (long long)t * DI);
        float uv = __ldg(uu + (long long)t * DI);
        float Bv = __ldg(db + t * NXP + DRK + s);
        float Cv = __ldg(db + t * NXP + DRK + DS + s);
        float dA = __expf(de * Av);
        h = fmaf(dA, h, de * uv * Bv);
        float v = h * Cv;
        v += __shfl_xor_sync(0xffffffffu, v, 8);
        v += __shfl_xor_sync(0xffffffffu, v, 4);
        v += __shfl_xor_sync(0xffffffffu, v, 2);
        v += __shfl_xor_sync(0xffffffffu, v, 1);
        if (s == 0) yy[(long long)t * DI] = fmaf(Dd, uv, v);
    }
}

// ---------------- gaussian masks ----------------
// dist[b,t] = || y[b,t,:] - y[b,ref,:] ||  (one warp per t)
__global__ void dist_kernel(const float* __restrict__ y, float* __restrict__ dist, int ref)
{
    int b = blockIdx.y;
    int t = blockIdx.x * 8 + (threadIdx.x >> 5);
    int lane = threadIdx.x & 31;
    if (t >= LC) return;
    const float* yt = y + ((long long)b * LC + t) * DI;
    const float* yr = y + ((long long)b * LC + ref) * DI;
    float acc = 0.f;
    for (int d = lane; d < DI; d += 32) {
        float df = yt[d] - yr[d];
        acc = fmaf(df, df, acc);
    }
    #pragma unroll
    for (int o = 16; o; o >>= 1) acc += __shfl_xor_sync(0xffffffffu, acc, o);
    if (lane == 0) dist[b * LC + t] = sqrtf(fmaxf(acc, 1e-12f));
}

// m[b,t] = l2norm_t( exp(-0.5 (t-ref)^2/si^2) * exp(-0.5 (d_t/sv)^2) )
// (the reference's two /sum normalizations cancel inside _l2norm)
__global__ void maskfin_kernel(const float* __restrict__ dist, float* __restrict__ m, int ref)
{
    __shared__ float red[512];
    int b = blockIdx.x;
    int tid = threadIdx.x;
    float s = 0.f;
    for (int t = tid; t < LC; t += 512) s += dist[b * LC + t];
    red[tid] = s; __syncthreads();
    for (int o = 256; o; o >>= 1) { if (tid < o) red[tid] += red[tid + o]; __syncthreads(); }
    float sigv = red[0] / (float)LC;
    __syncthreads();
    float si = ((float)ref * (float)(ref + 1) * 0.5f +
                (float)(LC - 1 - ref) * (float)(LC - ref) * 0.5f) / (float)LC;
    float c_i = 0.5f / (si * si);
    float c_v = 0.5f / (sigv * sigv);
    float nrm = 0.f;
    for (int t = tid; t < LC; t += 512) {
        float dt = (float)(t - ref);
        float dv = dist[b * LC + t];
        float p = expf(-dt * dt * c_i - dv * dv * c_v);
        m[b * LC + t] = p;
        nrm = fmaf(p, p, nrm);
    }
    red[tid] = nrm; __syncthreads();
    for (int o = 256; o; o >>= 1) { if (tid < o) red[tid] += red[tid + o]; __syncthreads(); }
    float inv = 1.f / fmaxf(sqrtf(red[0]), 1e-12f);
    __syncthreads();
    for (int t = tid; t < LC; t += 512) m[b * LC + t] *= inv;
}

// ycat = [ y_f * m_f , y_b * reverse(m_b) ]
__global__ void concat_kernel()
{
    int t = blockIdx.x, b = blockIdx.y, c = threadIdx.x;
    long long r = (long long)b * LC + t;
    g_ycat[r * (2 * DI) + c]      = g_yf[r * DI + c] * g_mf[b * LC + t];
    g_ycat[r * (2 * DI) + DI + c] = g_yb[r * DI + c] * g_mb[b * LC + (LC - 1 - t)];
}

__global__ void scale_y_kernel()
{
    int t = blockIdx.x, b = blockIdx.y, c = threadIdx.x;
    long long r = (long long)b * LC + t;
    g_y[r * DI + c] *= g_mc[b * LC + t];
}

// softmax over l for each (b, token t); writes Atok transposed (B, Stok, LC)
__global__ void softmax_kernel()
{
    __shared__ float sv[LC];
    __shared__ float red[256];
    int tt = blockIdx.x, b = blockIdx.y, tid = threadIdx.x;
    float mx = -1e30f;
    for (int l = tid; l < LC; l += 256) {
        float v = g_scores[((long long)b * LC + l) * Stok + tt];
        sv[l] = v; mx = fmaxf(mx, v);
    }
    red[tid] = mx; __syncthreads();
    for (int o = 128; o; o >>= 1) { if (tid < o) red[tid] = fmaxf(red[tid], red[tid + o]); __syncthreads(); }
    mx = red[0]; __syncthreads();
    float sum = 0.f;
    for (int l = tid; l < LC; l += 256) { float e = expf(sv[l] - mx); sv[l] = e; sum += e; }
    red[tid] = sum; __syncthreads();
    for (int o = 128; o; o >>= 1) { if (tid < o) red[tid] += red[tid + o]; __syncthreads(); }
    float inv = 1.f / red[0]; __syncthreads();
    for (int l = tid; l < LC; l += 256)
        g_atok[((long long)b * Stok + tt) * LC + l] = sv[l] * inv;
}

// ---------------- host launcher ----------------
static inline int ceildiv(int a, int b) { return (a + b - 1) / b; }

extern "C" void kernel_launch(void* const* d_in, const int* in_sizes, int n_in,
                              void* d_out, int out_size)
{
    const float* x        = (const float*)d_in[0];
    const float* W_in_x   = (const float*)d_in[1];
    const float* W_in_z   = (const float*)d_in[2];
    const float* conv_w_f = (const float*)d_in[3];
    const float* conv_b_f = (const float*)d_in[4];
    const float* conv_w_b = (const float*)d_in[5];
    const float* conv_b_b = (const float*)d_in[6];
    const float* W_xp_f   = (const float*)d_in[7];
    const float* b_xp_f   = (const float*)d_in[8];
    const float* W_dt_f   = (const float*)d_in[9];
    const float* b_dt_f   = (const float*)d_in[10];
    const float* A_log_f  = (const float*)d_in[11];
    const float* D_f      = (const float*)d_in[12];
    const float* W_xp_b   = (const float*)d_in[13];
    const float* b_xp_b   = (const float*)d_in[14];
    const float* W_dt_b   = (const float*)d_in[15];
    const float* b_dt_b   = (const float*)d_in[16];
    const float* A_log_b  = (const float*)d_in[17];
    const float* D_b      = (const float*)d_in[18];
    const float* W_pro_to = (const float*)d_in[19];
    const float* b_pro_to = (const float*)d_in[20];
    const float* token_wA = (const float*)d_in[21];
    const float* token_wV = (const float*)d_in[22];
    const float* W_out    = (const float*)d_in[23];
    float* out = (float*)d_out;

    float *xi, *uf, *ub, *dbcf, *dbcb, *def, *deb, *yf, *yb, *ycat, *yy;
    float *mf, *mb, *mc, *dist, *xp, *zp, *scores, *atok, *vv, *T;
    cudaGetSymbolAddress((void**)&xi,   g_xi);
    cudaGetSymbolAddress((void**)&uf,   g_uf);
    cudaGetSymbolAddress((void**)&ub,   g_ub);
    cudaGetSymbolAddress((void**)&dbcf, g_dbcf);
    cudaGetSymbolAddress((void**)&dbcb, g_dbcb);
    cudaGetSymbolAddress((void**)&def,  g_deltaf);
    cudaGetSymbolAddress((void**)&deb,  g_deltab);
    cudaGetSymbolAddress((void**)&yf,   g_yf);
    cudaGetSymbolAddress((void**)&yb,   g_yb);
    cudaGetSymbolAddress((void**)&ycat, g_ycat);
    cudaGetSymbolAddress((void**)&yy,   g_y);
    cudaGetSymbolAddress((void**)&mf,   g_mf);
    cudaGetSymbolAddress((void**)&mb,   g_mb);
    cudaGetSymbolAddress((void**)&mc,   g_mc);
    cudaGetSymbolAddress((void**)&dist, g_dist);
    cudaGetSymbolAddress((void**)&xp,   g_xp);
    cudaGetSymbolAddress((void**)&zp,   g_zp);
    cudaGetSymbolAddress((void**)&scores, g_scores);
    cudaGetSymbolAddress((void**)&atok, g_atok);
    cudaGetSymbolAddress((void**)&vv,   g_vv);
    cudaGetSymbolAddress((void**)&T,    g_T);

    dim3 thr(16, 16);
    const int ML = Bsz * Lseq;  // 16392
    const int MC = Bsz * LC;    // 8224

    // 1) xi = x @ W_in_x^T   (M=16392, N=512, K=256)
    sgemm_k<1><<<dim3(DI / BN, ceildiv(ML, BM), 1), thr>>>(
        x, W_in_x, nullptr, nullptr, xi, ML, DI, Dmod, Dmod, Dmod, DI, 0, 0, 0, 0, 0);

    // 2) pooled x, then zp = silu(xp @ W_in_z^T)
    pool_kernel<<<dim3(Stok, Bsz), Dmod>>>(x);
    sgemm_k<1><<<dim3(DI / BN, ceildiv(Bsz * Stok, BM), 1), thr>>>(
        xp, W_in_z, nullptr, nullptr, zp, Bsz * Stok, DI, Dmod, Dmod, Dmod, DI, 0, 0, 0, 0, 1);

    // 3) depthwise conv + silu, both directions
    conv_silu_kernel<<<dim3(LC, Bsz), DI>>>(xi, conv_w_f, conv_b_f, uf, 0);
    conv_silu_kernel<<<dim3(LC, Bsz), DI>>>(xi, conv_w_b, conv_b_b, ub, 1);

    // 4) dbc = u @ W_xp^T + b_xp   (N=48)
    sgemm_k<1><<<dim3(ceildiv(NXP, BN), ceildiv(MC, BM), 1), thr>>>(
        uf, W_xp_f, b_xp_f, nullptr, dbcf, MC, NXP, DI, DI, DI, NXP, 0, 0, 0, 0, 0);
    sgemm_k<1><<<dim3(ceildiv(NXP, BN), ceildiv(MC, BM), 1), thr>>>(
        ub, W_xp_b, b_xp_b, nullptr, dbcb, MC, NXP, DI, DI, DI, NXP, 0, 0, 0, 0, 0);

    // 5) delta = softplus(dr @ W_dt^T + b_dt)   (K=16 view of dbc, lda=48)
    sgemm_k<1><<<dim3(DI / BN, ceildiv(MC, BM), 1), thr>>>(
        dbcf, W_dt_f, b_dt_f, nullptr, def, MC, DI, DRK, NXP, DRK, DI, 0, 0, 0, 0, 2);
    sgemm_k<1><<<dim3(DI / BN, ceildiv(MC, BM), 1), thr>>>(
        dbcb, W_dt_b, b_dt_b, nullptr, deb, MC, DI, DRK, NXP, DRK, DI, 0, 0, 0, 0, 2);

    // 6) selective scans
    scan_kernel<<<Bsz * DI / 16, 256>>>(uf, def, dbcf, A_log_f, D_f, yf);
    scan_kernel<<<Bsz * DI / 16, 256>>>(ub, deb, dbcb, A_log_b, D_b, yb);

    // 7) masks on y_f, y_b (kind 'last', ref = LC-1)
    dist_kernel<<<dim3(ceildiv(LC, 8), Bsz), 256>>>(yf, dist, LC - 1);
    maskfin_kernel<<<Bsz, 512>>>(dist, mf, LC - 1);
    dist_kernel<<<dim3(ceildiv(LC, 8), Bsz), 256>>>(yb, dist, LC - 1);
    maskfin_kernel<<<Bsz, 512>>>(dist, mb, LC - 1);

    // 8) ycat = [y_f*m_f, y_b*rev(m_b)], then y = ycat @ W_pro_to^T + b
    concat_kernel<<<dim3(LC, Bsz), DI>>>();
    sgemm_k<1><<<dim3(DI / BN, ceildiv(MC, BM), 1), thr>>>(
        ycat, W_pro_to, b_pro_to, nullptr, yy, MC, DI, 2 * DI, 2 * DI, 2 * DI, DI, 0, 0, 0, 0, 0);

    // 9) center mask on y, scale in place (ref = (LC+1)//2 = 514)
    dist_kernel<<<dim3(ceildiv(LC, 8), Bsz), 256>>>(yy, dist, (LC + 1) / 2);
    maskfin_kernel<<<Bsz, 512>>>(dist, mc, (LC + 1) / 2);
    scale_y_kernel<<<dim3(LC, Bsz), DI>>>();

    // 10) scores = y @ token_wA^T  (N=64), softmax over l -> Atok (B,64,LC)
    sgemm_k<1><<<dim3(1, ceildiv(MC, BM), 1), thr>>>(
        yy, token_wA, nullptr, nullptr, scores, MC, Stok, DI, DI, DI, Stok, 0, 0, 0, 0, 0);
    softmax_kernel<<<dim3(Stok, Bsz), 256>>>();

    // 11) VV = y @ token_wV  (nn)
    sgemm_k<0><<<dim3(DI / BN, ceildiv(MC, BM), 1), thr>>>(
        yy, token_wV, nullptr, nullptr, vv, MC, DI, DI, DI, DI, DI, 0, 0, 0, 0, 0);

    // 12) T = (Atok @ VV) * zp   (batched over b, fused elementwise gate)
    sgemm_k<0><<<dim3(DI / BN, 1, Bsz), thr>>>(
        atok, vv, nullptr, zp, T, Stok, DI, LC, LC, DI, DI,
        (long long)Stok * LC, (long long)LC * DI, (long long)Stok * DI, (long long)Stok * DI, 0);

    // 13) out = T @ W_out^T   (M=512, N=256, K=512)
    sgemm_k<1><<<dim3(Dmod / BN, ceildiv(Bsz * Stok, BM), 1), thr>>>(
        T, W_out, nullptr, nullptr, out, Bsz * Stok, Dmod, DI, DI, DI, Dmod, 0, 0, 0, 0, 0);
}

// round 2
// speedup vs baseline: 1.1362x; 1.1362x over previous
#include <cuda_runtime.h>
#include <cuda_bf16.h>
#include <math.h>

// ---------------- problem constants ----------------
#define Bsz  8
#define Lseq 2049
#define Dmod 256
#define DI   512
#define DS   16
#define DRK  16
#define LB   1025    // per-branch input length (mid = L//2+1 = 1025)
#define LC   1028    // conv output length: 1025 + 2*3 - 4 + 1
#define Stok 64
#define NXP  48      // dt_rank + 2*d_state

// ---------------- scratch (device globals; no cudaMalloc allowed) ----------------
__device__ float g_xi[Bsz*Lseq*DI];
__device__ float g_uf[Bsz*LC*DI];
__device__ float g_ub[Bsz*LC*DI];
__device__ float g_dbcf[Bsz*LC*NXP];
__device__ float g_dbcb[Bsz*LC*NXP];
__device__ float g_deltaf[Bsz*LC*DI];
__device__ float g_deltab[Bsz*LC*DI];
__device__ float g_yf[Bsz*LC*DI];
__device__ float g_yb[Bsz*LC*DI];
__device__ float g_ycat[Bsz*LC*2*DI];
__device__ float g_y[Bsz*LC*DI];
__device__ float g_mf[Bsz*LC];
__device__ float g_mb[Bsz*LC];
__device__ float g_mc[Bsz*LC];
__device__ float g_dist[Bsz*LC];
__device__ float g_xp[Bsz*Stok*Dmod];
__device__ float g_zp[Bsz*Stok*DI];
__device__ float g_scores[Bsz*LC*Stok];
__device__ float g_atok[Bsz*Stok*LC];
__device__ float g_ty[Bsz*Stok*DI];
__device__ float g_T[Bsz*Stok*DI];

// ---------------- generic fp32 tiled GEMM (small/odd shapes) ----------------
// C[M,N] = A[M,K(lda)] * op(B) (+bias per col) (act) (* emul elementwise)
// TB=0: B is (K,N) row-major ldb; TB=1: B is (N,K) row-major ldb.
// act: 0 none, 1 silu, 2 softplus.  Batched via gridDim.z with strides.
#define BM 128
#define BN 64
#define BK 16

template<int TB>
__global__ __launch_bounds__(256)
void sgemm_k(const float* __restrict__ A, const float* __restrict__ Bm,
             const float* __restrict__ bias, const float* __restrict__ emul,
             float* __restrict__ C,
             int M, int N, int K, int lda, int ldb, int ldc,
             long long sA, long long sB, long long sC, long long sE,
             int act)
{
    __shared__ float As[BK][BM+1];
    __shared__ float Bs[BK][BN+1];
    int bz = blockIdx.z;
    A  += (long long)bz * sA;
    Bm += (long long)bz * sB;
    C  += (long long)bz * sC;
    const float* em = emul ? emul + (long long)bz * sE : nullptr;

    int row0 = blockIdx.y * BM;
    int col0 = blockIdx.x * BN;
    int tx = threadIdx.x, ty = threadIdx.y;
    int tid = ty * 16 + tx;

    float acc[8][4];
    #pragma unroll
    for (int i = 0; i < 8; i++)
        #pragma unroll
        for (int j = 0; j < 4; j++) acc[i][j] = 0.f;

    for (int k0 = 0; k0 < K; k0 += BK) {
        #pragma unroll
        for (int i = 0; i < 8; i++) {
            int idx = tid + i * 256;
            int m = idx >> 4, kk = idx & 15;
            int gm = row0 + m, gk = k0 + kk;
            float v = 0.f;
            if (gm < M && gk < K) v = A[(long long)gm * lda + gk];
            As[kk][m] = v;
        }
        #pragma unroll
        for (int i = 0; i < 4; i++) {
            int idx = tid + i * 256;
            float v = 0.f;
            if (TB == 0) {
                int kk = idx >> 6, n = idx & 63;
                int gk = k0 + kk, gn = col0 + n;
                if (gk < K && gn < N) v = Bm[(long long)gk * ldb + gn];
                Bs[kk][n] = v;
            } else {
                int n = idx >> 4, kk = idx & 15;
                int gn = col0 + n, gk = k0 + kk;
                if (gn < N && gk < K) v = Bm[(long long)gn * ldb + gk];
                Bs[kk][n] = v;
            }
        }
        __syncthreads();
        #pragma unroll
        for (int kk = 0; kk < BK; kk++) {
            float a[8], b[4];
            #pragma unroll
            for (int i = 0; i < 8; i++) a[i] = As[kk][ty * 8 + i];
            #pragma unroll
            for (int j = 0; j < 4; j++) b[j] = Bs[kk][tx * 4 + j];
            #pragma unroll
            for (int i = 0; i < 8; i++)
                #pragma unroll
                for (int j = 0; j < 4; j++)
                    acc[i][j] = fmaf(a[i], b[j], acc[i][j]);
        }
        __syncthreads();
    }

    #pragma unroll
    for (int i = 0; i < 8; i++) {
        int gm = row0 + ty * 8 + i;
        if (gm >= M) continue;
        #pragma unroll
        for (int j = 0; j < 4; j++) {
            int gn = col0 + tx * 4 + j;
            if (gn >= N) continue;
            float v = acc[i][j];
            if (bias) v += bias[gn];
            if (act == 1)      v = v / (1.f + expf(-v));
            else if (act == 2) v = (v > 20.f) ? v : log1pf(expf(v));
            if (em) v *= em[(long long)gm * ldc + gn];
            C[(long long)gm * ldc + gn] = v;
        }
    }
}

// ---------------- big fp32 GEMM: 128x128x8, 8x8 micro, dbuf smem ----------------
// C[M,N] = A[M,K] * B^T  (B is (N,K) row-major) + optional per-col bias.
// Requires: K % 8 == 0, lda/ldb % 4 == 0, ldc % 4 == 0, N % 128 == 0.
#define TBM 128
#define TBN 128
#define TBK 8

__global__ __launch_bounds__(256, 2)
void sgemm128_tb1(const float* __restrict__ A, const float* __restrict__ Bm,
                  const float* __restrict__ bias, float* __restrict__ C,
                  int M, int N, int K, int lda, int ldb, int ldc)
{
    __shared__ float As[2][TBK][TBM + 4];
    __shared__ float Bs[2][TBK][TBN + 4];

    int tid  = threadIdx.x;
    int row0 = blockIdx.y * TBM;
    int col0 = blockIdx.x * TBN;

    int lr = tid >> 1;           // 0..127
    int lk = (tid & 1) * 4;      // 0 or 4

    int gm = row0 + lr;
    int gn = col0 + lr;
    bool mok = gm < M;

    const float* Aptr = A + (long long)gm * lda + lk;
    const float* Bptr = Bm + (long long)gn * ldb + lk;

    float4 pa = make_float4(0.f, 0.f, 0.f, 0.f);
    float4 pb = make_float4(0.f, 0.f, 0.f, 0.f);
    if (mok) pa = *(const float4*)(Aptr);
    pb = *(const float4*)(Bptr);           // N % 128 == 0 -> always valid

    int tx = tid & 15;    // col group
    int ty = tid >> 4;    // row group

    float acc[8][8];
    #pragma unroll
    for (int i = 0; i < 8; i++)
        #pragma unroll
        for (int j = 0; j < 8; j++) acc[i][j] = 0.f;

    int buf = 0;
    for (int k0 = 0; k0 < K; k0 += TBK) {
        As[buf][lk + 0][lr] = pa.x;
        As[buf][lk + 1][lr] = pa.y;
        As[buf][lk + 2][lr] = pa.z;
        As[buf][lk + 3][lr] = pa.w;
        Bs[buf][lk + 0][lr] = pb.x;
        Bs[buf][lk + 1][lr] = pb.y;
        Bs[buf][lk + 2][lr] = pb.z;
        Bs[buf][lk + 3][lr] = pb.w;
        __syncthreads();

        if (k0 + TBK < K) {
            pa = make_float4(0.f, 0.f, 0.f, 0.f);
            if (mok) pa = *(const float4*)(Aptr + k0 + TBK);
            pb = *(const float4*)(Bptr + k0 + TBK);
        }

        #pragma unroll
        for (int kk = 0; kk < TBK; kk++) {
            float4 a0 = *(const float4*)&As[buf][kk][ty * 8];
            float4 a1 = *(const float4*)&As[buf][kk][ty * 8 + 4];
            float4 b0 = *(const float4*)&Bs[buf][kk][tx * 8];
            float4 b1 = *(const float4*)&Bs[buf][kk][tx * 8 + 4];
            float a[8] = {a0.x, a0.y, a0.z, a0.w, a1.x, a1.y, a1.z, a1.w};
            float b[8] = {b0.x, b0.y, b0.z, b0.w, b1.x, b1.y, b1.z, b1.w};
            #pragma unroll
            for (int i = 0; i < 8; i++)
                #pragma unroll
                for (int j = 0; j < 8; j++)
                    acc[i][j] = fmaf(a[i], b[j], acc[i][j]);
        }
        buf ^= 1;
    }

    float bsv[8];
    #pragma unroll
    for (int j = 0; j < 8; j++) bsv[j] = bias ? bias[col0 + tx * 8 + j] : 0.f;

    #pragma unroll
    for (int i = 0; i < 8; i++) {
        int m = row0 + ty * 8 + i;
        if (m >= M) continue;
        float4 v0 = make_float4(acc[i][0] + bsv[0], acc[i][1] + bsv[1],
                                acc[i][2] + bsv[2], acc[i][3] + bsv[3]);
        float4 v1 = make_float4(acc[i][4] + bsv[4], acc[i][5] + bsv[5],
                                acc[i][6] + bsv[6], acc[i][7] + bsv[7]);
        float* cp = C + (long long)m * ldc + col0 + tx * 8;
        *(float4*)(cp)     = v0;
        *(float4*)(cp + 4) = v1;
    }
}

// ---------------- pooling of x (P @ x) ----------------
__global__ void pool_kernel(const float* __restrict__ x)
{
    int s = blockIdx.x, b = blockIdx.y, d = threadIdx.x; // 256 threads
    int s0 = (s * Lseq) / Stok;
    int e  = ((s + 1) * Lseq + Stok - 1) / Stok;
    float acc = 0.f;
    for (int l = s0; l < e; l++) acc += x[((long long)b * Lseq + l) * Dmod + d];
    g_xp[((long long)b * Stok + s) * Dmod + d] = acc / (float)(e - s0);
}

// ---------------- depthwise conv (k=4, pad 3) + SiLU ----------------
__global__ void conv_silu_kernel(const float* __restrict__ xi, const float* __restrict__ w,
                                 const float* __restrict__ bias, float* __restrict__ out,
                                 int backward)
{
    int t = blockIdx.x;      // 0..LC-1
    int b = blockIdx.y;
    int c = threadIdx.x;     // 0..511
    float acc = bias[c];
    #pragma unroll
    for (int k = 0; k < 4; k++) {
        int i = t + k - 3;
        if (i >= 0 && i < LB) {
            int l = backward ? (Lseq - 1 - i) : i;
            acc = fmaf(w[c * 4 + k], xi[((long long)b * Lseq + l) * DI + c], acc);
        }
    }
    out[((long long)b * LC + t) * DI + c] = acc / (1.f + expf(-acc));
}

// ---------------- selective scan: 16 lanes per (b,d), one state per lane ----------------
__global__ __launch_bounds__(256)
void scan_kernel(const float* __restrict__ u, const float* __restrict__ delta,
                 const float* __restrict__ dbc, const float* __restrict__ A_log,
                 const float* __restrict__ Dp, float* __restrict__ y)
{
    int gid = blockIdx.x * 16 + (threadIdx.x >> 4);
    int s = threadIdx.x & 15;
    int b = gid >> 9;
    int d = gid & 511;
    float Av = -expf(A_log[d * 16 + s]);
    float Dd = Dp[d];
    float h = 0.f;
    const float* db = dbc + (long long)b * LC * NXP;
    const float* dl = delta + ((long long)b * LC) * DI + d;
    const float* uu = u     + ((long long)b * LC) * DI + d;
    float*       yy = y     + ((long long)b * LC) * DI + d;
    for (int t = 0; t < LC; t++) {
        float de = __ldg(dl + (long long)t * DI);
        float uv = __ldg(uu + (long long)t * DI);
        float Bv = __ldg(db + t * NXP + DRK + s);
        float Cv = __ldg(db + t * NXP + DRK + DS + s);
        float dA = __expf(de * Av);
        h = fmaf(dA, h, de * uv * Bv);
        float v = h * Cv;
        v += __shfl_xor_sync(0xffffffffu, v, 8);
        v += __shfl_xor_sync(0xffffffffu, v, 4);
        v += __shfl_xor_sync(0xffffffffu, v, 2);
        v += __shfl_xor_sync(0xffffffffu, v, 1);
        if (s == 0) yy[(long long)t * DI] = fmaf(Dd, uv, v);
    }
}

// ---------------- gaussian masks ----------------
__global__ void dist_kernel(const float* __restrict__ y, float* __restrict__ dist, int ref)
{
    int b = blockIdx.y;
    int t = blockIdx.x * 8 + (threadIdx.x >> 5);
    int lane = threadIdx.x & 31;
    if (t >= LC) return;
    const float* yt = y + ((long long)b * LC + t) * DI;
    const float* yr = y + ((long long)b * LC + ref) * DI;
    float acc = 0.f;
    for (int d = lane; d < DI; d += 32) {
        float df = yt[d] - yr[d];
        acc = fmaf(df, df, acc);
    }
    #pragma unroll
    for (int o = 16; o; o >>= 1) acc += __shfl_xor_sync(0xffffffffu, acc, o);
    if (lane == 0) dist[b * LC + t] = sqrtf(fmaxf(acc, 1e-12f));
}

__global__ void maskfin_kernel(const float* __restrict__ dist, float* __restrict__ m, int ref)
{
    __shared__ float red[512];
    int b = blockIdx.x;
    int tid = threadIdx.x;
    float s = 0.f;
    for (int t = tid; t < LC; t += 512) s += dist[b * LC + t];
    red[tid] = s; __syncthreads();
    for (int o = 256; o; o >>= 1) { if (tid < o) red[tid] += red[tid + o]; __syncthreads(); }
    float sigv = red[0] / (float)LC;
    __syncthreads();
    float si = ((float)ref * (float)(ref + 1) * 0.5f +
                (float)(LC - 1 - ref) * (float)(LC - ref) * 0.5f) / (float)LC;
    float c_i = 0.5f / (si * si);
    float c_v = 0.5f / (sigv * sigv);
    float nrm = 0.f;
    for (int t = tid; t < LC; t += 512) {
        float dt = (float)(t - ref);
        float dv = dist[b * LC + t];
        float p = expf(-dt * dt * c_i - dv * dv * c_v);
        m[b * LC + t] = p;
        nrm = fmaf(p, p, nrm);
    }
    red[tid] = nrm; __syncthreads();
    for (int o = 256; o; o >>= 1) { if (tid < o) red[tid] += red[tid + o]; __syncthreads(); }
    float inv = 1.f / fmaxf(sqrtf(red[0]), 1e-12f);
    __syncthreads();
    for (int t = tid; t < LC; t += 512) m[b * LC + t] *= inv;
}

// ycat = [ y_f * m_f , y_b * reverse(m_b) ]
__global__ void concat_kernel()
{
    int t = blockIdx.x, b = blockIdx.y, c = threadIdx.x;
    long long r = (long long)b * LC + t;
    g_ycat[r * (2 * DI) + c]      = g_yf[r * DI + c] * g_mf[b * LC + t];
    g_ycat[r * (2 * DI) + DI + c] = g_yb[r * DI + c] * g_mb[b * LC + (LC - 1 - t)];
}

__global__ void scale_y_kernel()
{
    int t = blockIdx.x, b = blockIdx.y, c = threadIdx.x;
    long long r = (long long)b * LC + t;
    g_y[r * DI + c] *= g_mc[b * LC + t];
}

// softmax over l for each (b, token t); writes Atok transposed (B, Stok, LC)
__global__ void softmax_kernel()
{
    __shared__ float sv[LC];
    __shared__ float red[256];
    int tt = blockIdx.x, b = blockIdx.y, tid = threadIdx.x;
    float mx = -1e30f;
    for (int l = tid; l < LC; l += 256) {
        float v = g_scores[((long long)b * LC + l) * Stok + tt];
        sv[l] = v; mx = fmaxf(mx, v);
    }
    red[tid] = mx; __syncthreads();
    for (int o = 128; o; o >>= 1) { if (tid < o) red[tid] = fmaxf(red[tid], red[tid + o]); __syncthreads(); }
    mx = red[0]; __syncthreads();
    float sum = 0.f;
    for (int l = tid; l < LC; l += 256) { float e = expf(sv[l] - mx); sv[l] = e; sum += e; }
    red[tid] = sum; __syncthreads();
    for (int o = 128; o; o >>= 1) { if (tid < o) red[tid] += red[tid + o]; __syncthreads(); }
    float inv = 1.f / red[0]; __syncthreads();
    for (int l = tid; l < LC; l += 256)
        g_atok[((long long)b * Stok + tt) * LC + l] = sv[l] * inv;
}

// ---------------- host launcher ----------------
static inline int ceildiv(int a, int b) { return (a + b - 1) / b; }

extern "C" void kernel_launch(void* const* d_in, const int* in_sizes, int n_in,
                              void* d_out, int out_size)
{
    const float* x        = (const float*)d_in[0];
    const float* W_in_x   = (const float*)d_in[1];
    const float* W_in_z   = (const float*)d_in[2];
    const float* conv_w_f = (const float*)d_in[3];
    const float* conv_b_f = (const float*)d_in[4];
    const float* conv_w_b = (const float*)d_in[5];
    const float* conv_b_b = (const float*)d_in[6];
    const float* W_xp_f   = (const float*)d_in[7];
    const float* b_xp_f   = (const float*)d_in[8];
    const float* W_dt_f   = (const float*)d_in[9];
    const float* b_dt_f   = (const float*)d_in[10];
    const float* A_log_f  = (const float*)d_in[11];
    const float* D_f      = (const float*)d_in[12];
    const float* W_xp_b   = (const float*)d_in[13];
    const float* b_xp_b   = (const float*)d_in[14];
    const float* W_dt_b   = (const float*)d_in[15];
    const float* b_dt_b   = (const float*)d_in[16];
    const float* A_log_b  = (const float*)d_in[17];
    const float* D_b      = (const float*)d_in[18];
    const float* W_pro_to = (const float*)d_in[19];
    const float* b_pro_to = (const float*)d_in[20];
    const float* token_wA = (const float*)d_in[21];
    const float* token_wV = (const float*)d_in[22];
    const float* W_out    = (const float*)d_in[23];
    float* out = (float*)d_out;

    float *xi, *uf, *ub, *dbcf, *dbcb, *def, *deb, *yf, *yb, *ycat, *yy;
    float *mf, *mb, *mc, *dist, *xp, *zp, *scores, *atok, *tyb, *T;
    cudaGetSymbolAddress((void**)&xi,   g_xi);
    cudaGetSymbolAddress((void**)&uf,   g_uf);
    cudaGetSymbolAddress((void**)&ub,   g_ub);
    cudaGetSymbolAddress((void**)&dbcf, g_dbcf);
    cudaGetSymbolAddress((void**)&dbcb, g_dbcb);
    cudaGetSymbolAddress((void**)&def,  g_deltaf);
    cudaGetSymbolAddress((void**)&deb,  g_deltab);
    cudaGetSymbolAddress((void**)&yf,   g_yf);
    cudaGetSymbolAddress((void**)&yb,   g_yb);
    cudaGetSymbolAddress((void**)&ycat, g_ycat);
    cudaGetSymbolAddress((void**)&yy,   g_y);
    cudaGetSymbolAddress((void**)&mf,   g_mf);
    cudaGetSymbolAddress((void**)&mb,   g_mb);
    cudaGetSymbolAddress((void**)&mc,   g_mc);
    cudaGetSymbolAddress((void**)&dist, g_dist);
    cudaGetSymbolAddress((void**)&xp,   g_xp);
    cudaGetSymbolAddress((void**)&zp,   g_zp);
    cudaGetSymbolAddress((void**)&scores, g_scores);
    cudaGetSymbolAddress((void**)&atok, g_atok);
    cudaGetSymbolAddress((void**)&tyb,  g_ty);
    cudaGetSymbolAddress((void**)&T,    g_T);

    dim3 thr(16, 16);
    const int ML = Bsz * Lseq;  // 16392
    const int MC = Bsz * LC;    // 8224

    // 1) xi = x @ W_in_x^T   (M=16392, N=512, K=256) -- big GEMM path
    sgemm128_tb1<<<dim3(DI / TBN, ceildiv(ML, TBM)), 256>>>(
        x, W_in_x, nullptr, xi, ML, DI, Dmod, Dmod, Dmod, DI);

    // 2) pooled x, then zp = silu(xp @ W_in_z^T)
    pool_kernel<<<dim3(Stok, Bsz), Dmod>>>(x);
    sgemm_k<1><<<dim3(DI / BN, ceildiv(Bsz * Stok, BM), 1), thr>>>(
        xp, W_in_z, nullptr, nullptr, zp, Bsz * Stok, DI, Dmod, Dmod, Dmod, DI, 0, 0, 0, 0, 1);

    // 3) depthwise conv + silu, both directions
    conv_silu_kernel<<<dim3(LC, Bsz), DI>>>(xi, conv_w_f, conv_b_f, uf, 0);
    conv_silu_kernel<<<dim3(LC, Bsz), DI>>>(xi, conv_w_b, conv_b_b, ub, 1);

    // 4) dbc = u @ W_xp^T + b_xp   (N=48)
    sgemm_k<1><<<dim3(ceildiv(NXP, BN), ceildiv(MC, BM), 1), thr>>>(
        uf, W_xp_f, b_xp_f, nullptr, dbcf, MC, NXP, DI, DI, DI, NXP, 0, 0, 0, 0, 0);
    sgemm_k<1><<<dim3(ceildiv(NXP, BN), ceildiv(MC, BM), 1), thr>>>(
        ub, W_xp_b, b_xp_b, nullptr, dbcb, MC, NXP, DI, DI, DI, NXP, 0, 0, 0, 0, 0);

    // 5) delta = softplus(dr @ W_dt^T + b_dt)   (K=16 view of dbc, lda=48)
    sgemm_k<1><<<dim3(DI / BN, ceildiv(MC, BM), 1), thr>>>(
        dbcf, W_dt_f, b_dt_f, nullptr, def, MC, DI, DRK, NXP, DRK, DI, 0, 0, 0, 0, 2);
    sgemm_k<1><<<dim3(DI / BN, ceildiv(MC, BM), 1), thr>>>(
        dbcb, W_dt_b, b_dt_b, nullptr, deb, MC, DI, DRK, NXP, DRK, DI, 0, 0, 0, 0, 2);

    // 6) selective scans
    scan_kernel<<<Bsz * DI / 16, 256>>>(uf, def, dbcf, A_log_f, D_f, yf);
    scan_kernel<<<Bsz * DI / 16, 256>>>(ub, deb, dbcb, A_log_b, D_b, yb);

    // 7) masks on y_f, y_b (kind 'last', ref = LC-1)
    dist_kernel<<<dim3(ceildiv(LC, 8), Bsz), 256>>>(yf, dist, LC - 1);
    maskfin_kernel<<<Bsz, 512>>>(dist, mf, LC - 1);
    dist_kernel<<<dim3(ceildiv(LC, 8), Bsz), 256>>>(yb, dist, LC - 1);
    maskfin_kernel<<<Bsz, 512>>>(dist, mb, LC - 1);

    // 8) ycat = [y_f*m_f, y_b*rev(m_b)], then y = ycat @ W_pro_to^T + b -- big GEMM
    concat_kernel<<<dim3(LC, Bsz), DI>>>();
    sgemm128_tb1<<<dim3(DI / TBN, ceildiv(MC, TBM)), 256>>>(
        ycat, W_pro_to, b_pro_to, yy, MC, DI, 2 * DI, 2 * DI, 2 * DI, DI);

    // 9) center mask on y, scale in place (ref = (LC+1)//2 = 514)
    dist_kernel<<<dim3(ceildiv(LC, 8), Bsz), 256>>>(yy, dist, (LC + 1) / 2);
    maskfin_kernel<<<Bsz, 512>>>(dist, mc, (LC + 1) / 2);
    scale_y_kernel<<<dim3(LC, Bsz), DI>>>();

    // 10) scores = y @ token_wA^T  (N=64), softmax over l -> Atok (B,64,LC)
    sgemm_k<1><<<dim3(1, ceildiv(MC, BM), 1), thr>>>(
        yy, token_wA, nullptr, nullptr, scores, MC, Stok, DI, DI, DI, Stok, 0, 0, 0, 0, 0);
    softmax_kernel<<<dim3(Stok, Bsz), 256>>>();

    // 11) Ty = Atok @ y   (associativity: T = (Atok @ y) @ wV)
    //     batched over b: M=64, N=512, K=1028
    sgemm_k<0><<<dim3(DI / BN, 1, Bsz), thr>>>(
        atok, yy, nullptr, nullptr, tyb, Stok, DI, LC, LC, DI, DI,
        (long long)Stok * LC, (long long)LC * DI, (long long)Stok * DI, 0, 0);

    // 12) T = (Ty @ token_wV) * zp   (batched over b, wV shared, fused gate)
    sgemm_k<0><<<dim3(DI / BN, 1, Bsz), thr>>>(
        tyb, token_wV, nullptr, zp, T, Stok, DI, DI, DI, DI, DI,
        (long long)Stok * DI, 0, (long long)Stok * DI, (long long)Stok * DI, 0);

    // 13) out = T @ W_out^T   (M=512, N=256, K=512)
    sgemm_k<1><<<dim3(Dmod / BN, ceildiv(Bsz * Stok, BM), 1), thr>>>(
        T, W_out, nullptr, nullptr, out, Bsz * Stok, Dmod, DI, DI, DI, Dmod, 0, 0, 0, 0, 0);
}

// round 3
// speedup vs baseline: 1.3511x; 1.1891x over previous
#include <cuda_runtime.h>
#include <cuda_bf16.h>
#include <math.h>
#include <stdint.h>

// ---------------- problem constants ----------------
#define Bsz  8
#define Lseq 2049
#define Dmod 256
#define DI   512
#define DS   16
#define DRK  16
#define LB   1025    // per-branch input length (mid = L//2+1 = 1025)
#define LC   1028    // conv output length: 1025 + 2*3 - 4 + 1
#define Stok 64
#define NXP  48      // dt_rank + 2*d_state

// ---------------- scratch (device globals; no cudaMalloc allowed) ----------------
__device__ float g_xi[Bsz*Lseq*DI];
__device__ float g_uf[Bsz*LC*DI];
__device__ float g_ub[Bsz*LC*DI];
__device__ float g_dbcf[Bsz*LC*NXP];
__device__ float g_dbcb[Bsz*LC*NXP];
__device__ float g_deltaf[Bsz*LC*DI];
__device__ float g_deltab[Bsz*LC*DI];
__device__ float g_yf[Bsz*LC*DI];
__device__ float g_yb[Bsz*LC*DI];
__device__ float g_ycat[Bsz*LC*2*DI];
__device__ float g_y[Bsz*LC*DI];
__device__ float g_mf[Bsz*LC];
__device__ float g_mb[Bsz*LC];
__device__ float g_mc[Bsz*LC];
__device__ float g_dist[Bsz*LC];
__device__ float g_xp[Bsz*Stok*Dmod];
__device__ float g_zp[Bsz*Stok*DI];
__device__ float g_scores[Bsz*LC*Stok];
__device__ float g_atok[Bsz*Stok*LC];
__device__ float g_ty[Bsz*Stok*DI];
__device__ float g_T[Bsz*Stok*DI];

// =====================================================================
// Tensor-core GEMM: C[M,N] = A[M,K] * B^T (+bias), fp32 in/out.
// bf16 hi/lo split (3 HMMAs) for ~fp32 accuracy on the tensor pipe.
// Requirements: N % 128 == 0, K % 16 == 0, lda/ldb % 4 == 0, ldc % 2 == 0.
// Tile: 128x128 CTA, 8 warps of 64x32, BK=16, ldmatrix from padded smem.
// =====================================================================
#define SAS 24   // smem row stride in bf16 (48B: conflict-free for ldmatrix)

__device__ __forceinline__ uint32_t s2u(const void* p) {
    return (uint32_t)__cvta_generic_to_shared(p);
}

__device__ __forceinline__ void ldsm4(uint32_t r[4], uint32_t addr) {
    asm volatile("ldmatrix.sync.aligned.m8n8.x4.shared.b16 {%0,%1,%2,%3}, [%4];"
                 : "=r"(r[0]), "=r"(r[1]), "=r"(r[2]), "=r"(r[3]) : "r"(addr));
}

__device__ __forceinline__ void mma16816(float c[4], const uint32_t a[4],
                                         uint32_t b0, uint32_t b1) {
    asm volatile(
        "mma.sync.aligned.m16n8k16.row.col.f32.bf16.bf16.f32 "
        "{%0,%1,%2,%3},{%4,%5,%6,%7},{%8,%9},{%0,%1,%2,%3};"
        : "+f"(c[0]), "+f"(c[1]), "+f"(c[2]), "+f"(c[3])
        : "r"(a[0]), "r"(a[1]), "r"(a[2]), "r"(a[3]), "r"(b0), "r"(b1));
}

__global__ __launch_bounds__(256, 2)
void hgemm_split_tb1(const float* __restrict__ A, const float* __restrict__ Bm,
                     const float* __restrict__ bias, float* __restrict__ C,
                     int M, int N, int K, int lda, int ldb, int ldc)
{
    __shared__ __align__(16) __nv_bfloat16 As_hi[128][SAS];
    __shared__ __align__(16) __nv_bfloat16 As_lo[128][SAS];
    __shared__ __align__(16) __nv_bfloat16 Bs_hi[128][SAS];
    __shared__ __align__(16) __nv_bfloat16 Bs_lo[128][SAS];

    int tid  = threadIdx.x;
    int lane = tid & 31;
    int wid  = tid >> 5;
    int wm0  = (wid >> 2) * 64;   // warp row origin within tile
    int wn0  = (wid & 3) * 32;    // warp col origin within tile
    int row0 = blockIdx.y * 128;
    int col0 = blockIdx.x * 128;

    // ldmatrix lane addressing: lanes 0-15 -> rows, col 0; 16-31 -> rows, col 8
    int lr = lane & 15;
    int lc = (lane >> 4) * 8;

    float acc[4][4][4];
    #pragma unroll
    for (int i = 0; i < 4; i++)
        #pragma unroll
        for (int j = 0; j < 4; j++)
            #pragma unroll
            for (int q = 0; q < 4; q++) acc[i][j][q] = 0.f;

    for (int k0 = 0; k0 < K; k0 += 16) {
        // ---- load + convert A tile (128x16 fp32 -> bf16 hi/lo) ----
        #pragma unroll
        for (int i = 0; i < 2; i++) {
            int idx = tid + i * 256;        // 0..511
            int r  = idx >> 2;
            int cg = (idx & 3) * 4;
            int gm = row0 + r;
            float4 v = make_float4(0.f, 0.f, 0.f, 0.f);
            if (gm < M) v = *(const float4*)(A + (long long)gm * lda + k0 + cg);
            __nv_bfloat16 h0 = __float2bfloat16(v.x);
            __nv_bfloat16 h1 = __float2bfloat16(v.y);
            __nv_bfloat16 h2 = __float2bfloat16(v.z);
            __nv_bfloat16 h3 = __float2bfloat16(v.w);
            __nv_bfloat16 l0 = __float2bfloat16(v.x - __bfloat162float(h0));
            __nv_bfloat16 l1 = __float2bfloat16(v.y - __bfloat162float(h1));
            __nv_bfloat16 l2 = __float2bfloat16(v.z - __bfloat162float(h2));
            __nv_bfloat16 l3 = __float2bfloat16(v.w - __bfloat162float(h3));
            *(__nv_bfloat162*)&As_hi[r][cg]     = __nv_bfloat162(h0, h1);
            *(__nv_bfloat162*)&As_hi[r][cg + 2] = __nv_bfloat162(h2, h3);
            *(__nv_bfloat162*)&As_lo[r][cg]     = __nv_bfloat162(l0, l1);
            *(__nv_bfloat162*)&As_lo[r][cg + 2] = __nv_bfloat162(l2, l3);
        }
        // ---- load + convert B tile (128x16 fp32 from (N,K) row-major) ----
        #pragma unroll
        for (int i = 0; i < 2; i++) {
            int idx = tid + i * 256;
            int r  = idx >> 2;
            int cg = (idx & 3) * 4;
            int gn = col0 + r;              // always < N (N % 128 == 0)
            float4 v = *(const float4*)(Bm + (long long)gn * ldb + k0 + cg);
            __nv_bfloat16 h0 = __float2bfloat16(v.x);
            __nv_bfloat16 h1 = __float2bfloat16(v.y);
            __nv_bfloat16 h2 = __float2bfloat16(v.z);
            __nv_bfloat16 h3 = __float2bfloat16(v.w);
            __nv_bfloat16 l0 = __float2bfloat16(v.x - __bfloat162float(h0));
            __nv_bfloat16 l1 = __float2bfloat16(v.y - __bfloat162float(h1));
            __nv_bfloat16 l2 = __float2bfloat16(v.z - __bfloat162float(h2));
            __nv_bfloat16 l3 = __float2bfloat16(v.w - __bfloat162float(h3));
            *(__nv_bfloat162*)&Bs_hi[r][cg]     = __nv_bfloat162(h0, h1);
            *(__nv_bfloat162*)&Bs_hi[r][cg + 2] = __nv_bfloat162(h2, h3);
            *(__nv_bfloat162*)&Bs_lo[r][cg]     = __nv_bfloat162(l0, l1);
            *(__nv_bfloat162*)&Bs_lo[r][cg + 2] = __nv_bfloat162(l2, l3);
        }
        __syncthreads();

        // ---- B fragments (n16 groups x {hi,lo}) ----
        uint32_t bh[2][4], bl[2][4];
        #pragma unroll
        for (int ng = 0; ng < 2; ng++) {
            ldsm4(bh[ng], s2u(&Bs_hi[wn0 + ng * 16 + lr][lc]));
            ldsm4(bl[ng], s2u(&Bs_lo[wn0 + ng * 16 + lr][lc]));
        }
        // ---- A fragments per m-tile, then 3-split MMAs ----
        #pragma unroll
        for (int mt = 0; mt < 4; mt++) {
            uint32_t ah[4], al[4];
            ldsm4(ah, s2u(&As_hi[wm0 + mt * 16 + lr][lc]));
            ldsm4(al, s2u(&As_lo[wm0 + mt * 16 + lr][lc]));
            #pragma unroll
            for (int nt = 0; nt < 4; nt++) {
                int ng = nt >> 1, sl = nt & 1;
                mma16816(acc[mt][nt], ah, bh[ng][sl], bh[ng][sl + 2]);
                mma16816(acc[mt][nt], ah, bl[ng][sl], bl[ng][sl + 2]);
                mma16816(acc[mt][nt], al, bh[ng][sl], bh[ng][sl + 2]);
            }
        }
        __syncthreads();
    }

    // ---- epilogue ----
    int g = lane >> 2, t = lane & 3;
    #pragma unroll
    for (int mt = 0; mt < 4; mt++) {
        #pragma unroll
        for (int nt = 0; nt < 4; nt++) {
            int cb = col0 + wn0 + nt * 8 + 2 * t;
            float b0 = bias ? bias[cb]     : 0.f;
            float b1 = bias ? bias[cb + 1] : 0.f;
            int r0 = row0 + wm0 + mt * 16 + g;
            if (r0 < M) {
                float2 v = make_float2(acc[mt][nt][0] + b0, acc[mt][nt][1] + b1);
                *(float2*)(C + (long long)r0 * ldc + cb) = v;
            }
            int r1 = r0 + 8;
            if (r1 < M) {
                float2 v = make_float2(acc[mt][nt][2] + b0, acc[mt][nt][3] + b1);
                *(float2*)(C + (long long)r1 * ldc + cb) = v;
            }
        }
    }
}

// ---------------- generic fp32 tiled GEMM (small/odd shapes) ----------------
#define BM 128
#define BN 64
#define BK 16

template<int TB>
__global__ __launch_bounds__(256)
void sgemm_k(const float* __restrict__ A, const float* __restrict__ Bm,
             const float* __restrict__ bias, const float* __restrict__ emul,
             float* __restrict__ C,
             int M, int N, int K, int lda, int ldb, int ldc,
             long long sA, long long sB, long long sC, long long sE,
             int act)
{
    __shared__ float As[BK][BM+1];
    __shared__ float Bs[BK][BN+1];
    int bz = blockIdx.z;
    A  += (long long)bz * sA;
    Bm += (long long)bz * sB;
    C  += (long long)bz * sC;
    const float* em = emul ? emul + (long long)bz * sE : nullptr;

    int row0 = blockIdx.y * BM;
    int col0 = blockIdx.x * BN;
    int tx = threadIdx.x, ty = threadIdx.y;
    int tid = ty * 16 + tx;

    float acc[8][4];
    #pragma unroll
    for (int i = 0; i < 8; i++)
        #pragma unroll
        for (int j = 0; j < 4; j++) acc[i][j] = 0.f;

    for (int k0 = 0; k0 < K; k0 += BK) {
        #pragma unroll
        for (int i = 0; i < 8; i++) {
            int idx = tid + i * 256;
            int m = idx >> 4, kk = idx & 15;
            int gm = row0 + m, gk = k0 + kk;
            float v = 0.f;
            if (gm < M && gk < K) v = A[(long long)gm * lda + gk];
            As[kk][m] = v;
        }
        #pragma unroll
        for (int i = 0; i < 4; i++) {
            int idx = tid + i * 256;
            float v = 0.f;
            if (TB == 0) {
                int kk = idx >> 6, n = idx & 63;
                int gk = k0 + kk, gn = col0 + n;
                if (gk < K && gn < N) v = Bm[(long long)gk * ldb + gn];
                Bs[kk][n] = v;
            } else {
                int n = idx >> 4, kk = idx & 15;
                int gn = col0 + n, gk = k0 + kk;
                if (gn < N && gk < K) v = Bm[(long long)gn * ldb + gk];
                Bs[kk][n] = v;
            }
        }
        __syncthreads();
        #pragma unroll
        for (int kk = 0; kk < BK; kk++) {
            float a[8], b[4];
            #pragma unroll
            for (int i = 0; i < 8; i++) a[i] = As[kk][ty * 8 + i];
            #pragma unroll
            for (int j = 0; j < 4; j++) b[j] = Bs[kk][tx * 4 + j];
            #pragma unroll
            for (int i = 0; i < 8; i++)
                #pragma unroll
                for (int j = 0; j < 4; j++)
                    acc[i][j] = fmaf(a[i], b[j], acc[i][j]);
        }
        __syncthreads();
    }

    #pragma unroll
    for (int i = 0; i < 8; i++) {
        int gm = row0 + ty * 8 + i;
        if (gm >= M) continue;
        #pragma unroll
        for (int j = 0; j < 4; j++) {
            int gn = col0 + tx * 4 + j;
            if (gn >= N) continue;
            float v = acc[i][j];
            if (bias) v += bias[gn];
            if (act == 1)      v = v / (1.f + expf(-v));
            else if (act == 2) v = (v > 20.f) ? v : log1pf(expf(v));
            if (em) v *= em[(long long)gm * ldc + gn];
            C[(long long)gm * ldc + gn] = v;
        }
    }
}

// ---------------- pooling of x (P @ x) ----------------
__global__ void pool_kernel(const float* __restrict__ x)
{
    int s = blockIdx.x, b = blockIdx.y, d = threadIdx.x; // 256 threads
    int s0 = (s * Lseq) / Stok;
    int e  = ((s + 1) * Lseq + Stok - 1) / Stok;
    float acc = 0.f;
    for (int l = s0; l < e; l++) acc += x[((long long)b * Lseq + l) * Dmod + d];
    g_xp[((long long)b * Stok + s) * Dmod + d] = acc / (float)(e - s0);
}

// ---------------- depthwise conv (k=4, pad 3) + SiLU ----------------
__global__ void conv_silu_kernel(const float* __restrict__ xi, const float* __restrict__ w,
                                 const float* __restrict__ bias, float* __restrict__ out,
                                 int backward)
{
    int t = blockIdx.x;      // 0..LC-1
    int b = blockIdx.y;
    int c = threadIdx.x;     // 0..511
    float acc = bias[c];
    #pragma unroll
    for (int k = 0; k < 4; k++) {
        int i = t + k - 3;
        if (i >= 0 && i < LB) {
            int l = backward ? (Lseq - 1 - i) : i;
            acc = fmaf(w[c * 4 + k], xi[((long long)b * Lseq + l) * DI + c], acc);
        }
    }
    out[((long long)b * LC + t) * DI + c] = acc / (1.f + expf(-acc));
}

// ---------------- selective scan: 16 lanes per (b,d), one state per lane ----------------
__global__ __launch_bounds__(256)
void scan_kernel(const float* __restrict__ u, const float* __restrict__ delta,
                 const float* __restrict__ dbc, const float* __restrict__ A_log,
                 const float* __restrict__ Dp, float* __restrict__ y)
{
    int gid = blockIdx.x * 16 + (threadIdx.x >> 4);
    int s = threadIdx.x & 15;
    int b = gid >> 9;
    int d = gid & 511;
    float Av = -expf(A_log[d * 16 + s]);
    float Dd = Dp[d];
    float h = 0.f;
    const float* db = dbc + (long long)b * LC * NXP;
    const float* dl = delta + ((long long)b * LC) * DI + d;
    const float* uu = u     + ((long long)b * LC) * DI + d;
    float*       yy = y     + ((long long)b * LC) * DI + d;
    for (int t = 0; t < LC; t++) {
        float de = __ldg(dl + (long long)t * DI);
        float uv = __ldg(uu + (long long)t * DI);
        float Bv = __ldg(db + t * NXP + DRK + s);
        float Cv = __ldg(db + t * NXP + DRK + DS + s);
        float dA = __expf(de * Av);
        h = fmaf(dA, h, de * uv * Bv);
        float v = h * Cv;
        v += __shfl_xor_sync(0xffffffffu, v, 8);
        v += __shfl_xor_sync(0xffffffffu, v, 4);
        v += __shfl_xor_sync(0xffffffffu, v, 2);
        v += __shfl_xor_sync(0xffffffffu, v, 1);
        if (s == 0) yy[(long long)t * DI] = fmaf(Dd, uv, v);
    }
}

// ---------------- gaussian masks ----------------
__global__ void dist_kernel(const float* __restrict__ y, float* __restrict__ dist, int ref)
{
    int b = blockIdx.y;
    int t = blockIdx.x * 8 + (threadIdx.x >> 5);
    int lane = threadIdx.x & 31;
    if (t >= LC) return;
    const float* yt = y + ((long long)b * LC + t) * DI;
    const float* yr = y + ((long long)b * LC + ref) * DI;
    float acc = 0.f;
    for (int d = lane; d < DI; d += 32) {
        float df = yt[d] - yr[d];
        acc = fmaf(df, df, acc);
    }
    #pragma unroll
    for (int o = 16; o; o >>= 1) acc += __shfl_xor_sync(0xffffffffu, acc, o);
    if (lane == 0) dist[b * LC + t] = sqrtf(fmaxf(acc, 1e-12f));
}

__global__ void maskfin_kernel(const float* __restrict__ dist, float* __restrict__ m, int ref)
{
    __shared__ float red[512];
    int b = blockIdx.x;
    int tid = threadIdx.x;
    float s = 0.f;
    for (int t = tid; t < LC; t += 512) s += dist[b * LC + t];
    red[tid] = s; __syncthreads();
    for (int o = 256; o; o >>= 1) { if (tid < o) red[tid] += red[tid + o]; __syncthreads(); }
    float sigv = red[0] / (float)LC;
    __syncthreads();
    float si = ((float)ref * (float)(ref + 1) * 0.5f +
                (float)(LC - 1 - ref) * (float)(LC - ref) * 0.5f) / (float)LC;
    float c_i = 0.5f / (si * si);
    float c_v = 0.5f / (sigv * sigv);
    float nrm = 0.f;
    for (int t = tid; t < LC; t += 512) {
        float dt = (float)(t - ref);
        float dv = dist[b * LC + t];
        float p = expf(-dt * dt * c_i - dv * dv * c_v);
        m[b * LC + t] = p;
        nrm = fmaf(p, p, nrm);
    }
    red[tid] = nrm; __syncthreads();
    for (int o = 256; o; o >>= 1) { if (tid < o) red[tid] += red[tid + o]; __syncthreads(); }
    float inv = 1.f / fmaxf(sqrtf(red[0]), 1e-12f);
    __syncthreads();
    for (int t = tid; t < LC; t += 512) m[b * LC + t] *= inv;
}

// ycat = [ y_f * m_f , y_b * reverse(m_b) ]
__global__ void concat_kernel()
{
    int t = blockIdx.x, b = blockIdx.y, c = threadIdx.x;
    long long r = (long long)b * LC + t;
    g_ycat[r * (2 * DI) + c]      = g_yf[r * DI + c] * g_mf[b * LC + t];
    g_ycat[r * (2 * DI) + DI + c] = g_yb[r * DI + c] * g_mb[b * LC + (LC - 1 - t)];
}

__global__ void scale_y_kernel()
{
    int t = blockIdx.x, b = blockIdx.y, c = threadIdx.x;
    long long r = (long long)b * LC + t;
    g_y[r * DI + c] *= g_mc[b * LC + t];
}

// softmax over l for each (b, token t); writes Atok transposed (B, Stok, LC)
__global__ void softmax_kernel()
{
    __shared__ float sv[LC];
    __shared__ float red[256];
    int tt = blockIdx.x, b = blockIdx.y, tid = threadIdx.x;
    float mx = -1e30f;
    for (int l = tid; l < LC; l += 256) {
        float v = g_scores[((long long)b * LC + l) * Stok + tt];
        sv[l] = v; mx = fmaxf(mx, v);
    }
    red[tid] = mx; __syncthreads();
    for (int o = 128; o; o >>= 1) { if (tid < o) red[tid] = fmaxf(red[tid], red[tid + o]); __syncthreads(); }
    mx = red[0]; __syncthreads();
    float sum = 0.f;
    for (int l = tid; l < LC; l += 256) { float e = expf(sv[l] - mx); sv[l] = e; sum += e; }
    red[tid] = sum; __syncthreads();
    for (int o = 128; o; o >>= 1) { if (tid < o) red[tid] += red[tid + o]; __syncthreads(); }
    float inv = 1.f / red[0]; __syncthreads();
    for (int l = tid; l < LC; l += 256)
        g_atok[((long long)b * Stok + tt) * LC + l] = sv[l] * inv;
}

// ---------------- host launcher ----------------
static inline int ceildiv(int a, int b) { return (a + b - 1) / b; }

extern "C" void kernel_launch(void* const* d_in, const int* in_sizes, int n_in,
                              void* d_out, int out_size)
{
    const float* x        = (const float*)d_in[0];
    const float* W_in_x   = (const float*)d_in[1];
    const float* W_in_z   = (const float*)d_in[2];
    const float* conv_w_f = (const float*)d_in[3];
    const float* conv_b_f = (const float*)d_in[4];
    const float* conv_w_b = (const float*)d_in[5];
    const float* conv_b_b = (const float*)d_in[6];
    const float* W_xp_f   = (const float*)d_in[7];
    const float* b_xp_f   = (const float*)d_in[8];
    const float* W_dt_f   = (const float*)d_in[9];
    const float* b_dt_f   = (const float*)d_in[10];
    const float* A_log_f  = (const float*)d_in[11];
    const float* D_f      = (const float*)d_in[12];
    const float* W_xp_b   = (const float*)d_in[13];
    const float* b_xp_b   = (const float*)d_in[14];
    const float* W_dt_b   = (const float*)d_in[15];
    const float* b_dt_b   = (const float*)d_in[16];
    const float* A_log_b  = (const float*)d_in[17];
    const float* D_b      = (const float*)d_in[18];
    const float* W_pro_to = (const float*)d_in[19];
    const float* b_pro_to = (const float*)d_in[20];
    const float* token_wA = (const float*)d_in[21];
    const float* token_wV = (const float*)d_in[22];
    const float* W_out    = (const float*)d_in[23];
    float* out = (float*)d_out;

    float *xi, *uf, *ub, *dbcf, *dbcb, *def, *deb, *yf, *yb, *ycat, *yy;
    float *mf, *mb, *mc, *dist, *xp, *zp, *scores, *atok, *tyb, *T;
    cudaGetSymbolAddress((void**)&xi,   g_xi);
    cudaGetSymbolAddress((void**)&uf,   g_uf);
    cudaGetSymbolAddress((void**)&ub,   g_ub);
    cudaGetSymbolAddress((void**)&dbcf, g_dbcf);
    cudaGetSymbolAddress((void**)&dbcb, g_dbcb);
    cudaGetSymbolAddress((void**)&def,  g_deltaf);
    cudaGetSymbolAddress((void**)&deb,  g_deltab);
    cudaGetSymbolAddress((void**)&yf,   g_yf);
    cudaGetSymbolAddress((void**)&yb,   g_yb);
    cudaGetSymbolAddress((void**)&ycat, g_ycat);
    cudaGetSymbolAddress((void**)&yy,   g_y);
    cudaGetSymbolAddress((void**)&mf,   g_mf);
    cudaGetSymbolAddress((void**)&mb,   g_mb);
    cudaGetSymbolAddress((void**)&mc,   g_mc);
    cudaGetSymbolAddress((void**)&dist, g_dist);
    cudaGetSymbolAddress((void**)&xp,   g_xp);
    cudaGetSymbolAddress((void**)&zp,   g_zp);
    cudaGetSymbolAddress((void**)&scores, g_scores);
    cudaGetSymbolAddress((void**)&atok, g_atok);
    cudaGetSymbolAddress((void**)&tyb,  g_ty);
    cudaGetSymbolAddress((void**)&T,    g_T);

    dim3 thr(16, 16);
    const int ML = Bsz * Lseq;  // 16392
    const int MC = Bsz * LC;    // 8224

    // 1) xi = x @ W_in_x^T   (M=16392, N=512, K=256) -- tensor-core path
    hgemm_split_tb1<<<dim3(DI / 128, ceildiv(ML, 128)), 256>>>(
        x, W_in_x, nullptr, xi, ML, DI, Dmod, Dmod, Dmod, DI);

    // 2) pooled x, then zp = silu(xp @ W_in_z^T)
    pool_kernel<<<dim3(Stok, Bsz), Dmod>>>(x);
    sgemm_k<1><<<dim3(DI / BN, ceildiv(Bsz * Stok, BM), 1), thr>>>(
        xp, W_in_z, nullptr, nullptr, zp, Bsz * Stok, DI, Dmod, Dmod, Dmod, DI, 0, 0, 0, 0, 1);

    // 3) depthwise conv + silu, both directions
    conv_silu_kernel<<<dim3(LC, Bsz), DI>>>(xi, conv_w_f, conv_b_f, uf, 0);
    conv_silu_kernel<<<dim3(LC, Bsz), DI>>>(xi, conv_w_b, conv_b_b, ub, 1);

    // 4) dbc = u @ W_xp^T + b_xp   (N=48)
    sgemm_k<1><<<dim3(ceildiv(NXP, BN), ceildiv(MC, BM), 1), thr>>>(
        uf, W_xp_f, b_xp_f, nullptr, dbcf, MC, NXP, DI, DI, DI, NXP, 0, 0, 0, 0, 0);
    sgemm_k<1><<<dim3(ceildiv(NXP, BN), ceildiv(MC, BM), 1), thr>>>(
        ub, W_xp_b, b_xp_b, nullptr, dbcb, MC, NXP, DI, DI, DI, NXP, 0, 0, 0, 0, 0);

    // 5) delta = softplus(dr @ W_dt^T + b_dt)   (K=16 view of dbc, lda=48)
    sgemm_k<1><<<dim3(DI / BN, ceildiv(MC, BM), 1), thr>>>(
        dbcf, W_dt_f, b_dt_f, nullptr, def, MC, DI, DRK, NXP, DRK, DI, 0, 0, 0, 0, 2);
    sgemm_k<1><<<dim3(DI / BN, ceildiv(MC, BM), 1), thr>>>(
        dbcb, W_dt_b, b_dt_b, nullptr, deb, MC, DI, DRK, NXP, DRK, DI, 0, 0, 0, 0, 2);

    // 6) selective scans
    scan_kernel<<<Bsz * DI / 16, 256>>>(uf, def, dbcf, A_log_f, D_f, yf);
    scan_kernel<<<Bsz * DI / 16, 256>>>(ub, deb, dbcb, A_log_b, D_b, yb);

    // 7) masks on y_f, y_b (kind 'last', ref = LC-1)
    dist_kernel<<<dim3(ceildiv(LC, 8), Bsz), 256>>>(yf, dist, LC - 1);
    maskfin_kernel<<<Bsz, 512>>>(dist, mf, LC - 1);
    dist_kernel<<<dim3(ceildiv(LC, 8), Bsz), 256>>>(yb, dist, LC - 1);
    maskfin_kernel<<<Bsz, 512>>>(dist, mb, LC - 1);

    // 8) ycat = [y_f*m_f, y_b*rev(m_b)], then y = ycat @ W_pro_to^T + b -- tensor core
    concat_kernel<<<dim3(LC, Bsz), DI>>>();
    hgemm_split_tb1<<<dim3(DI / 128, ceildiv(MC, 128)), 256>>>(
        ycat, W_pro_to, b_pro_to, yy, MC, DI, 2 * DI, 2 * DI, 2 * DI, DI);

    // 9) center mask on y, scale in place (ref = (LC+1)//2 = 514)
    dist_kernel<<<dim3(ceildiv(LC, 8), Bsz), 256>>>(yy, dist, (LC + 1) / 2);
    maskfin_kernel<<<Bsz, 512>>>(dist, mc, (LC + 1) / 2);
    scale_y_kernel<<<dim3(LC, Bsz), DI>>>();

    // 10) scores = y @ token_wA^T  (N=64), softmax over l -> Atok (B,64,LC)
    sgemm_k<1><<<dim3(1, ceildiv(MC, BM), 1), thr>>>(
        yy, token_wA, nullptr, nullptr, scores, MC, Stok, DI, DI, DI, Stok, 0, 0, 0, 0, 0);
    softmax_kernel<<<dim3(Stok, Bsz), 256>>>();

    // 11) Ty = Atok @ y   (associativity: T = (Atok @ y) @ wV)
    sgemm_k<0><<<dim3(DI / BN, 1, Bsz), thr>>>(
        atok, yy, nullptr, nullptr, tyb, Stok, DI, LC, LC, DI, DI,
        (long long)Stok * LC, (long long)LC * DI, (long long)Stok * DI, 0, 0);

    // 12) T = (Ty @ token_wV) * zp   (batched over b, wV shared, fused gate)
    sgemm_k<0><<<dim3(DI / BN, 1, Bsz), thr>>>(
        tyb, token_wV, nullptr, zp, T, Stok, DI, DI, DI, DI, DI,
        (long long)Stok * DI, 0, (long long)Stok * DI, (long long)Stok * DI, 0);

    // 13) out = T @ W_out^T   (M=512, N=256, K=512) -- tensor core
    hgemm_split_tb1<<<dim3(Dmod / 128, ceildiv(Bsz * Stok, 128)), 256>>>(
        T, W_out, nullptr, out, Bsz * Stok, Dmod, DI, DI, DI, Dmod);
}